// round 15
// baseline (speedup 1.0000x reference)
#include <cuda_runtime.h>
#include <cuda_fp16.h>
#include <math.h>
#include <stdint.h>

// ---------------- problem constants ----------------
#define NBLK 4
#define Bd   4
#define Sd   4096
#define Dd   1024
#define Ad   1024
#define FFd  4096
#define Md   (Bd*Sd)          // 16384 rows
#define RSPLIT 128

// ---------------- scratch (device globals; allocation-free) ----------------
__device__ float g_bqkv[NBLK*3072];
__device__ __align__(256) __half g_qkvh[(size_t)Md*3072];
__device__ __align__(256) __half g_xh[(size_t)Md*Dd];     // current x (fp16)
__device__ __align__(256) __half g_th[(size_t)Md*Dd];     // pre-LN activations (O path)
__device__ __align__(256) __half g_vh[(size_t)Md*Ad];
__device__ __align__(256) __half g_hh[(size_t)Md*FFd];
__device__ __align__(256) float  g_p0[(size_t)Md*Dd];     // FF2 split-K partials
__device__ __align__(256) float  g_p1[(size_t)Md*Dd];
// fp16 weights (transposed [N,K]): per block 12M halves
// slots (1M units): qkv@0 (3M), o@3 (1M), w1@4 (4M), w2@8 (4M)
__device__ __align__(256) __half g_wf[(size_t)NBLK*12*1024*1024];
__device__ float g_pkv[RSPLIT*Bd*Ad], g_pks[RSPLIT*Bd*Ad];
__device__ float g_kv[Bd*Ad], g_ks[Bd*Ad];

#define WOFF(b, slot) ((size_t)(b)*12*1024*1024 + (size_t)(slot)*1024*1024)

// ---------------- PTX helpers (baseline PTX only) ----------------
__device__ __forceinline__ uint32_t smem_to_u32(const void* p) {
    uint32_t a;
    asm("{ .reg .u64 t; cvta.to.shared.u64 t, %1; cvt.u32.u64 %0, t; }" : "=r"(a) : "l"(p));
    return a;
}
__device__ __forceinline__ void cp16(uint32_t saddr, const void* gaddr) {
    asm volatile("cp.async.cg.shared.global [%0], [%1], 16;" :: "r"(saddr), "l"(gaddr) : "memory");
}
#define CP_COMMIT()  asm volatile("cp.async.commit_group;" ::: "memory")
#define CP_WAIT(n)   asm volatile("cp.async.wait_group %0;" :: "n"(n) : "memory")

__device__ __forceinline__ void ldsm4(uint32_t* r, uint32_t addr) {
    asm volatile("ldmatrix.sync.aligned.m8n8.x4.shared.b16 {%0,%1,%2,%3}, [%4];"
                 : "=r"(r[0]), "=r"(r[1]), "=r"(r[2]), "=r"(r[3]) : "r"(addr));
}
__device__ __forceinline__ void mma16816h(float* c, const uint32_t* a, const uint32_t* b) {
    asm volatile("mma.sync.aligned.m16n8k16.row.col.f32.f16.f16.f32 "
                 "{%0,%1,%2,%3}, {%4,%5,%6,%7}, {%8,%9}, {%0,%1,%2,%3};"
                 : "+f"(c[0]), "+f"(c[1]), "+f"(c[2]), "+f"(c[3])
                 : "r"(a[0]), "r"(a[1]), "r"(a[2]), "r"(a[3]), "r"(b[0]), "r"(b[1]));
}

// ---------------- math helpers ----------------
__device__ __forceinline__ float fast_rcp(float y) {
    float r = __uint_as_float(0x7EF311C3u - __float_as_uint(y));
    r = r * (2.0f - y * r);
    r = r * (2.0f - y * r);
    return r;
}
__device__ __forceinline__ float gelu_f(float x) {
    float u = 0.7978845608028654f * (x + 0.044715f * x * x * x);
    float uc = fminf(u, 9.0f);
    float e = exp2f(2.8853900817779268f * uc);   // e^(2u)
    float t = 1.0f - 2.0f * fast_rcp(e + 1.0f);
    return 0.5f * x * (1.0f + t);
}
__device__ __forceinline__ float act_apply(float c, int ACT) {
    if (ACT == 1) return (c > 0.0f) ? (c + 1.0f) : __expf(c);   // elu+1
    if (ACT == 2) return gelu_f(c);
    if (ACT == 3) return gelu_f(gelu_f(c));
    return c;
}

// ================= 1-product fp16 HMMA GEMM (fp16 out) =================
#define BKg    64
#define ROWB   144                  // 128B data + 16B pad -> conflict-free ldmatrix
#define TILEB  (128*ROWB)           // 18432 B
#define STAGEB (2*TILEB)            // A, W = 36864 B
#define GEMM_SMEM (2*STAGEB)        // 73728 B per CTA -> 2 CTAs/SM

template<int ACT>
__global__ void __launch_bounds__(256, 2)
gemm_mma(const __half* __restrict__ Ax, const __half* __restrict__ Bf,
         const float* __restrict__ bias, __half* __restrict__ Ch,
         int K, int N)
{
    extern __shared__ char smem[];
    const uint32_t sb = smem_to_u32(smem);
    const int tid = threadIdx.x, lane = tid & 31, warp = tid >> 5;
    const int wm = warp >> 2, wn = warp & 3;
    const int bx = blockIdx.x, by = blockIdx.y;

    float acc[4][4][4];
    #pragma unroll
    for (int i = 0; i < 4; i++)
        #pragma unroll
        for (int j = 0; j < 4; j++)
            #pragma unroll
            for (int k = 0; k < 4; k++) acc[i][j][k] = 0.0f;

    const __half* gp0 = Ax + (size_t)by*128*K;
    const __half* gp1 = Bf + (size_t)bx*128*K;

    auto load_stage = [&](int s, int kt) {
        #pragma unroll
        for (int i = 0; i < 8; i++) {
            int cid  = tid + i*256;
            int t    = cid >> 10;
            int slot = cid & 1023;
            int row  = slot >> 3;
            int c    = slot & 7;
            uint32_t sa = sb + s*STAGEB + t*TILEB + row*ROWB + c*16;
            const __half* g = (t == 0 ? gp0 : gp1);
            cp16(sa, g + (size_t)row*K + kt + c*8);
        }
        CP_COMMIT();
    };

    auto compute = [&](int s) {
        const uint32_t base = sb + s*STAGEB;
        const int l16 = lane & 15, lh = lane >> 4;
        const int brow = ((lane >> 4) & 1)*8 + (lane & 7);
        const int bc16 = (lane >> 3) & 1;
        #pragma unroll
        for (int ks = 0; ks < 4; ks++) {
            uint32_t ar[4][4], br[4][2];
            #pragma unroll
            for (int mi = 0; mi < 4; mi++) {
                uint32_t ad = base + (uint32_t)(wm*64 + mi*16 + l16)*ROWB + (ks*2 + lh)*16;
                ldsm4(ar[mi], ad);
            }
            #pragma unroll
            for (int np = 0; np < 2; np++) {
                uint32_t bd = base + TILEB
                            + (uint32_t)(wn*32 + np*16 + brow)*ROWB + (ks*2 + bc16)*16;
                ldsm4(&br[np*2][0], bd);
            }
            #pragma unroll
            for (int mi = 0; mi < 4; mi++)
                #pragma unroll
                for (int ni = 0; ni < 4; ni++)
                    mma16816h(acc[mi][ni], ar[mi], br[ni]);
        }
    };

    const int nk = K / BKg;
    load_stage(0, 0);
    for (int c = 0; c < nk; c++) {
        CP_WAIT(0);
        __syncthreads();
        if (c + 1 < nk) load_stage((c + 1) & 1, (c + 1) * BKg);
        compute(c & 1);
    }

    const int actm = (ACT == 4) ? ((bx*128 < 2048) ? 1 : 0) : ACT;
    const int row0 = by*128 + wm*64, col0 = bx*128 + wn*32;
    const int cl = (lane & 3) * 2, rl = lane >> 2;
    #pragma unroll
    for (int ni = 0; ni < 4; ni++) {
        const int gc = col0 + ni*8 + cl;
        const float b0 = bias[gc], b1 = bias[gc+1];
        #pragma unroll
        for (int mi = 0; mi < 4; mi++) {
            const int gr = row0 + mi*16 + rl;
            float v0 = act_apply(acc[mi][ni][0] + b0, actm);
            float v1 = act_apply(acc[mi][ni][1] + b1, actm);
            float v2 = act_apply(acc[mi][ni][2] + b0, actm);
            float v3 = act_apply(acc[mi][ni][3] + b1, actm);
            __half2 hp0 = __halves2half2(__float2half_rn(v0), __float2half_rn(v1));
            __half2 hp1 = __halves2half2(__float2half_rn(v2), __float2half_rn(v3));
            *(uint32_t*)(Ch + (size_t)gr*N + gc)     = *(uint32_t*)&hp0;
            *(uint32_t*)(Ch + (size_t)(gr+8)*N + gc) = *(uint32_t*)&hp1;
        }
    }
}

// ============ split-K=2 GEMM for FF2: raw fp32 partials, no bias/act ========
// grid (N/128, M/128, 2); z selects K-half and partial buffer.
__global__ void __launch_bounds__(256, 2)
gemm_splitk(const __half* __restrict__ Ax, const __half* __restrict__ Bf,
            float* __restrict__ P0, float* __restrict__ P1,
            int K, int N)
{
    extern __shared__ char smem[];
    const uint32_t sb = smem_to_u32(smem);
    const int tid = threadIdx.x, lane = tid & 31, warp = tid >> 5;
    const int wm = warp >> 2, wn = warp & 3;
    const int bx = blockIdx.x, by = blockIdx.y, bz = blockIdx.z;
    const int kh = K >> 1;                       // K half
    const int k0off = bz * kh;

    float acc[4][4][4];
    #pragma unroll
    for (int i = 0; i < 4; i++)
        #pragma unroll
        for (int j = 0; j < 4; j++)
            #pragma unroll
            for (int k = 0; k < 4; k++) acc[i][j][k] = 0.0f;

    const __half* gp0 = Ax + (size_t)by*128*K + k0off;
    const __half* gp1 = Bf + (size_t)bx*128*K + k0off;

    auto load_stage = [&](int s, int kt) {
        #pragma unroll
        for (int i = 0; i < 8; i++) {
            int cid  = tid + i*256;
            int t    = cid >> 10;
            int slot = cid & 1023;
            int row  = slot >> 3;
            int c    = slot & 7;
            uint32_t sa = sb + s*STAGEB + t*TILEB + row*ROWB + c*16;
            const __half* g = (t == 0 ? gp0 : gp1);
            cp16(sa, g + (size_t)row*K + kt + c*8);
        }
        CP_COMMIT();
    };

    auto compute = [&](int s) {
        const uint32_t base = sb + s*STAGEB;
        const int l16 = lane & 15, lh = lane >> 4;
        const int brow = ((lane >> 4) & 1)*8 + (lane & 7);
        const int bc16 = (lane >> 3) & 1;
        #pragma unroll
        for (int ks = 0; ks < 4; ks++) {
            uint32_t ar[4][4], br[4][2];
            #pragma unroll
            for (int mi = 0; mi < 4; mi++) {
                uint32_t ad = base + (uint32_t)(wm*64 + mi*16 + l16)*ROWB + (ks*2 + lh)*16;
                ldsm4(ar[mi], ad);
            }
            #pragma unroll
            for (int np = 0; np < 2; np++) {
                uint32_t bd = base + TILEB
                            + (uint32_t)(wn*32 + np*16 + brow)*ROWB + (ks*2 + bc16)*16;
                ldsm4(&br[np*2][0], bd);
            }
            #pragma unroll
            for (int mi = 0; mi < 4; mi++)
                #pragma unroll
                for (int ni = 0; ni < 4; ni++)
                    mma16816h(acc[mi][ni], ar[mi], br[ni]);
        }
    };

    const int nk = kh / BKg;
    load_stage(0, 0);
    for (int c = 0; c < nk; c++) {
        CP_WAIT(0);
        __syncthreads();
        if (c + 1 < nk) load_stage((c + 1) & 1, (c + 1) * BKg);
        compute(c & 1);
    }

    float* P = bz ? P1 : P0;
    const int row0 = by*128 + wm*64, col0 = bx*128 + wn*32;
    const int cl = (lane & 3) * 2, rl = lane >> 2;
    #pragma unroll
    for (int ni = 0; ni < 4; ni++) {
        const int gc = col0 + ni*8 + cl;
        #pragma unroll
        for (int mi = 0; mi < 4; mi++) {
            const int gr = row0 + mi*16 + rl;
            *(float2*)(P + (size_t)gr*N + gc)     = make_float2(acc[mi][ni][0], acc[mi][ni][1]);
            *(float2*)(P + (size_t)(gr+8)*N + gc) = make_float2(acc[mi][ni][2], acc[mi][ni][3]);
        }
    }
}

// ================= prep kernels (3 launches -> GEMM at profiled slot 3) ======
#define PREP_WTILES 12288
__global__ void __launch_bounds__(256)
prep_w(const float* __restrict__ Wq, const float* __restrict__ Wk,
       const float* __restrict__ Wv, const float* __restrict__ Wo,
       const float* __restrict__ W1, const float* __restrict__ W2)
{
    const int t = blockIdx.x, tid = threadIdx.x;
    __shared__ float s[32][133];
    const int i = t / 3072, r = t % 3072;
    const float* src; int K, N, kb, nb; size_t doff;
    if (r < 1024) {
        const int m = r >> 8, tile = r & 255;
        src = (m==0 ? Wq : m==1 ? Wk : m==2 ? Wv : Wo) + (size_t)i*1024*1024;
        K = 1024; N = 1024; doff = WOFF(i, m);
        kb = tile >> 3; nb = tile & 7;
    } else if (r < 2048) {
        const int tile = r - 1024;
        src = W1 + (size_t)i*4*1024*1024;
        K = 1024; N = 4096; doff = WOFF(i, 4);
        kb = tile >> 5; nb = tile & 31;
    } else {
        const int tile = r - 2048;
        src = W2 + (size_t)i*4*1024*1024;
        K = 4096; N = 1024; doff = WOFF(i, 8);
        kb = tile >> 3; nb = tile & 7;
    }
    const int k0 = kb*32, n0 = nb*128;
    #pragma unroll
    for (int j = 0; j < 4; j++) {
        int q  = tid + j*256;
        int rr = q >> 5;
        int cc = (q & 31) * 4;
        float4 v = *(const float4*)(src + (size_t)(k0+rr)*N + n0 + cc);
        s[rr][cc]   = v.x;
        s[rr][cc+1] = v.y;
        s[rr][cc+2] = v.z;
        s[rr][cc+3] = v.w;
    }
    __syncthreads();
    const int n = tid >> 1, kk = (tid & 1) * 16;
    __half hb[16];
    #pragma unroll
    for (int e = 0; e < 16; e++) hb[e] = __float2half_rn(s[kk + e][n]);
    __half* Th = g_wf + doff + (size_t)(n0+n)*K + k0 + kk;
    *(uint4*)(Th)     = *(uint4*)(hb);
    *(uint4*)(Th + 8) = *(uint4*)(hb + 8);
}

__global__ void __launch_bounds__(256)
prep_x(const float* __restrict__ x)
{
    const size_t c = blockIdx.x;
    const float4* x4 = (const float4*)x;
    #pragma unroll
    for (int j = 0; j < 2; j++) {
        size_t id = c*512 + threadIdx.x + j*256;
        float4 v = x4[id];
        __half h[4];
        h[0] = __float2half_rn(v.x);
        h[1] = __float2half_rn(v.y);
        h[2] = __float2half_rn(v.z);
        h[3] = __float2half_rn(v.w);
        *(uint2*)(g_xh + id*4) = *(uint2*)h;
    }
}

__global__ void __launch_bounds__(256)
prep_b(const float* __restrict__ bq, const float* __restrict__ bk,
       const float* __restrict__ bv)
{
    #pragma unroll
    for (int j = 0; j < 8; j++) {
        int id = blockIdx.x*2048 + threadIdx.x + j*256;
        int i  = id / 3072, n = id % 3072;
        float v = (n < 1024) ? bq[i*1024 + n]
                : (n < 2048) ? bk[i*1024 + n - 1024]
                             : bv[i*1024 + n - 2048];
        g_bqkv[id] = v;
    }
}

// ---------------- KV / Ksum reduction over g_qkvh (fp16, stride 3072) -------
__global__ void __launch_bounds__(256)
reduce_stage1(const __half* __restrict__ qkv)
{
    const int h = blockIdx.x * 256 + threadIdx.x;
    const int split = blockIdx.y;
    const int b = h >> 10, hh = h & 1023;
    const int chunk = Sd / RSPLIT;                  // 32
    const size_t base = ((size_t)b * Sd + (size_t)split * chunk) * 3072 + hh;
    float kv = 0.0f, ks = 0.0f;
    #pragma unroll 4
    for (int s = 0; s < chunk; s++) {
        float kk = __half2float(qkv[base + (size_t)s * 3072 + 1024]);
        float vv = __half2float(qkv[base + (size_t)s * 3072 + 2048]);
        kv = fmaf(kk, vv, kv);
        ks += kk;
    }
    g_pkv[(size_t)split * (Bd*Ad) + h] = kv;
    g_pks[(size_t)split * (Bd*Ad) + h] = ks;
}
__global__ void __launch_bounds__(256) reduce_stage2()
{
    const int tid = threadIdx.x;
    const int h = blockIdx.x * 64 + (tid >> 2);
    const int p = tid & 3;
    float kv = 0.0f, ks = 0.0f;
    #pragma unroll
    for (int s = p; s < RSPLIT; s += 4) {
        kv += g_pkv[(size_t)s * (Bd*Ad) + h];
        ks += g_pks[(size_t)s * (Bd*Ad) + h];
    }
    kv += __shfl_xor_sync(0xffffffffu, kv, 1);
    kv += __shfl_xor_sync(0xffffffffu, kv, 2);
    ks += __shfl_xor_sync(0xffffffffu, ks, 1);
    ks += __shfl_xor_sync(0xffffffffu, ks, 2);
    if (p == 0) { g_kv[h] = kv; g_ks[h] = ks; }
}

// ---------------- V' = Q*KV/(Q*Ksum+1e-6) -> fp16 (vectorized x4) -----------
__global__ void __launch_bounds__(256)
attn_v(const __half* __restrict__ qkv, __half* __restrict__ vh)
{
    const int idx4 = blockIdx.x * 256 + threadIdx.x;
    const int row = idx4 >> 8, hq = (idx4 & 255) * 4;
    const int b   = row >> 12;
    uint2 qraw = *(const uint2*)(qkv + (size_t)row*3072 + hq);
    __half2 q01 = *(__half2*)&qraw.x, q23 = *(__half2*)&qraw.y;
    float4 kvv = *(const float4*)(g_kv + b*Ad + hq);
    float4 ksv = *(const float4*)(g_ks + b*Ad + hq);
    float Q0 = __low2float(q01), Q1 = __high2float(q01);
    float Q2 = __low2float(q23), Q3 = __high2float(q23);
    float V0 = Q0 * kvv.x / (Q0 * ksv.x + 1e-6f);
    float V1 = Q1 * kvv.y / (Q1 * ksv.y + 1e-6f);
    float V2 = Q2 * kvv.z / (Q2 * ksv.z + 1e-6f);
    float V3 = Q3 * kvv.w / (Q3 * ksv.w + 1e-6f);
    __half2 o01 = __halves2half2(__float2half_rn(V0), __float2half_rn(V1));
    __half2 o23 = __halves2half2(__float2half_rn(V2), __float2half_rn(V3));
    uint2 ov = make_uint2(*(uint32_t*)&o01, *(uint32_t*)&o23);
    *(uint2*)(vh + (size_t)row*Ad + hq) = ov;
}

// ---------------- LN1: LN(a + r)*s + b; fp16 a, fp16 r ----------------------
__global__ void __launch_bounds__(256)
add_layernorm(const __half* __restrict__ a, const __half* __restrict__ r,
              const float* __restrict__ s, const float* __restrict__ b,
              __half* __restrict__ oh)
{
    __shared__ float sm[8];
    const int tid = threadIdx.x;
    const size_t base = (size_t)blockIdx.x * Dd;

    float v[4];
    float lsum = 0.0f;
    #pragma unroll
    for (int j = 0; j < 2; j++) {
        int i = tid*2 + j*512;
        __half2 av = *(const __half2*)(a + base + i);
        __half2 rv = *(const __half2*)(r + base + i);
        v[j*2]   = __low2float(av)  + __low2float(rv);
        v[j*2+1] = __high2float(av) + __high2float(rv);
        lsum += v[j*2] + v[j*2+1];
    }
    #pragma unroll
    for (int o = 16; o > 0; o >>= 1) lsum += __shfl_xor_sync(0xffffffffu, lsum, o);
    if ((tid & 31) == 0) sm[tid >> 5] = lsum;
    __syncthreads();
    float tot = 0.0f;
    #pragma unroll
    for (int w = 0; w < 8; w++) tot += sm[w];
    const float mean = tot * (1.0f / Dd);
    __syncthreads();

    float lvar = 0.0f;
    #pragma unroll
    for (int j = 0; j < 4; j++) { float d = v[j] - mean; lvar += d*d; }
    #pragma unroll
    for (int o = 16; o > 0; o >>= 1) lvar += __shfl_xor_sync(0xffffffffu, lvar, o);
    if ((tid & 31) == 0) sm[tid >> 5] = lvar;
    __syncthreads();
    float vtot = 0.0f;
    #pragma unroll
    for (int w = 0; w < 8; w++) vtot += sm[w];
    const float rstd = rsqrtf(vtot * (1.0f / Dd) + 1e-6f);

    #pragma unroll
    for (int j = 0; j < 2; j++) {
        int i = tid*2 + j*512;
        float o0 = (v[j*2]   - mean) * rstd * s[i]   + b[i];
        float o1 = (v[j*2+1] - mean) * rstd * s[i+1] + b[i+1];
        __half2 ov = __halves2half2(__float2half_rn(o0), __float2half_rn(o1));
        *(__half2*)(oh + base + i) = ov;
    }
}

// -------- LN2 + split-K fixup: f = gelu(p0+p1+bias); LN(f + r) --------------
__global__ void __launch_bounds__(256)
add_layernorm_fix(const float* __restrict__ p0, const float* __restrict__ p1,
                  const float* __restrict__ bias,
                  const __half* __restrict__ r,
                  const float* __restrict__ s, const float* __restrict__ b,
                  __half* __restrict__ oh, float* __restrict__ outf)
{
    __shared__ float sm[8];
    const int tid = threadIdx.x;
    const size_t base = (size_t)blockIdx.x * Dd;

    float v[4];
    float lsum = 0.0f;
    #pragma unroll
    for (int j = 0; j < 2; j++) {
        int i = tid*2 + j*512;
        float2 a0 = *(const float2*)(p0 + base + i);
        float2 a1 = *(const float2*)(p1 + base + i);
        __half2 rv = *(const __half2*)(r + base + i);
        float f0 = gelu_f(a0.x + a1.x + bias[i]);
        float f1 = gelu_f(a0.y + a1.y + bias[i+1]);
        v[j*2]   = f0 + __low2float(rv);
        v[j*2+1] = f1 + __high2float(rv);
        lsum += v[j*2] + v[j*2+1];
    }
    #pragma unroll
    for (int o = 16; o > 0; o >>= 1) lsum += __shfl_xor_sync(0xffffffffu, lsum, o);
    if ((tid & 31) == 0) sm[tid >> 5] = lsum;
    __syncthreads();
    float tot = 0.0f;
    #pragma unroll
    for (int w = 0; w < 8; w++) tot += sm[w];
    const float mean = tot * (1.0f / Dd);
    __syncthreads();

    float lvar = 0.0f;
    #pragma unroll
    for (int j = 0; j < 4; j++) { float d = v[j] - mean; lvar += d*d; }
    #pragma unroll
    for (int o = 16; o > 0; o >>= 1) lvar += __shfl_xor_sync(0xffffffffu, lvar, o);
    if ((tid & 31) == 0) sm[tid >> 5] = lvar;
    __syncthreads();
    float vtot = 0.0f;
    #pragma unroll
    for (int w = 0; w < 8; w++) vtot += sm[w];
    const float rstd = rsqrtf(vtot * (1.0f / Dd) + 1e-6f);

    #pragma unroll
    for (int j = 0; j < 2; j++) {
        int i = tid*2 + j*512;
        float o0 = (v[j*2]   - mean) * rstd * s[i]   + b[i];
        float o1 = (v[j*2+1] - mean) * rstd * s[i+1] + b[i+1];
        __half2 ov = __halves2half2(__float2half_rn(o0), __float2half_rn(o1));
        *(__half2*)(oh + base + i) = ov;
        if (outf) *(float2*)(outf + base + i) = make_float2(o0, o1);
    }
}

// ---------------- launcher ----------------
extern "C" void kernel_launch(void* const* d_in, const int* in_sizes, int n_in,
                              void* d_out, int out_size)
{
    const float* x     = (const float*)d_in[0];
    const float* Wq    = (const float*)d_in[1];
    const float* bq    = (const float*)d_in[2];
    const float* Wk    = (const float*)d_in[3];
    const float* bk    = (const float*)d_in[4];
    const float* Wv    = (const float*)d_in[5];
    const float* bv    = (const float*)d_in[6];
    const float* Wo    = (const float*)d_in[7];
    const float* bo    = (const float*)d_in[8];
    const float* ln1_s = (const float*)d_in[9];
    const float* ln1_b = (const float*)d_in[10];
    const float* W1    = (const float*)d_in[11];
    const float* b1    = (const float*)d_in[12];
    const float* W2    = (const float*)d_in[13];
    const float* b2    = (const float*)d_in[14];
    const float* ln2_s = (const float*)d_in[15];
    const float* ln2_b = (const float*)d_in[16];
    float* out = (float*)d_out;

    float *gbq, *gp0, *gp1;
    __half *gqkvh, *gxh, *gth, *gvh, *ghh, *gwf;
    cudaGetSymbolAddress((void**)&gbq,   g_bqkv);
    cudaGetSymbolAddress((void**)&gp0,   g_p0);
    cudaGetSymbolAddress((void**)&gp1,   g_p1);
    cudaGetSymbolAddress((void**)&gqkvh, g_qkvh);
    cudaGetSymbolAddress((void**)&gxh,   g_xh);
    cudaGetSymbolAddress((void**)&gth,   g_th);
    cudaGetSymbolAddress((void**)&gvh,   g_vh);
    cudaGetSymbolAddress((void**)&ghh,   g_hh);
    cudaGetSymbolAddress((void**)&gwf,   g_wf);

    cudaFuncSetAttribute(gemm_mma<4>, cudaFuncAttributeMaxDynamicSharedMemorySize, GEMM_SMEM);
    cudaFuncSetAttribute(gemm_mma<3>, cudaFuncAttributeMaxDynamicSharedMemorySize, GEMM_SMEM);
    cudaFuncSetAttribute(gemm_mma<2>, cudaFuncAttributeMaxDynamicSharedMemorySize, GEMM_SMEM);
    cudaFuncSetAttribute(gemm_splitk, cudaFuncAttributeMaxDynamicSharedMemorySize, GEMM_SMEM);

    // prep as 3 launches (0,1,2) so the QKV GEMM lands at the profiled slot
    prep_w<<<PREP_WTILES, 256>>>(Wq, Wk, Wv, Wo, W1, W2);
    prep_x<<<8192, 256>>>(x);
    prep_b<<<6, 256>>>(bq, bk, bv);

    const dim3 gQKV(3072/128, Md/128);       // 24 x 128
    const dim3 gA(Ad/128,  Md/128);          // 8 x 128
    const dim3 gF(FFd/128, Md/128);          // 32 x 128
    const dim3 gFF2(Dd/128, Md/128, 2);      // 8 x 128 x 2 (split-K)

    for (int i = 0; i < NBLK; i++) {
        // fused QKV: N=3072, elu+1 on cols<2048; fp16 output
        gemm_mma<4><<<gQKV, 256, GEMM_SMEM>>>(gxh, gwf + WOFF(i,0),
                                              gbq + i*3072, gqkvh, Dd, 3072);

        reduce_stage1<<<dim3((Bd*Ad)/256, RSPLIT), 256>>>(gqkvh);
        reduce_stage2<<<(Bd*Ad)/64, 256>>>();
        attn_v<<<((size_t)Md*Ad/4)/256, 256>>>(gqkvh, gvh);

        // a = gelu(gelu(V@Wo + bo))  -> fp16
        gemm_mma<3><<<gA, 256, GEMM_SMEM>>>(gvh, gwf + WOFF(i,3),
                                            bo + (size_t)i*Dd, gth, Ad, Dd);
        add_layernorm<<<Md, 256>>>(gth, gxh, ln1_s + (size_t)i*Dd, ln1_b + (size_t)i*Dd,
                                   gxh);

        // h = gelu(x@W1+b1) -> fp16 ; FF2 split-K=2 raw partials
        gemm_mma<2><<<gF, 256, GEMM_SMEM>>>(gxh, gwf + WOFF(i,4),
                                            b1 + (size_t)i*FFd, ghh, Dd, FFd);
        gemm_splitk<<<gFF2, 256, GEMM_SMEM>>>(ghh, gwf + WOFF(i,8), gp0, gp1, FFd, Dd);

        // x = LN(gelu(p0+p1+b2) + x); final block also writes fp32 output
        float* outf = (i == NBLK-1) ? out : nullptr;
        add_layernorm_fix<<<Md, 256>>>(gp0, gp1, b2 + (size_t)i*Dd, gxh,
                                       ln2_s + (size_t)i*Dd, ln2_b + (size_t)i*Dd,
                                       gxh, outf);
    }
}

// round 16
// speedup vs baseline: 1.0256x; 1.0256x over previous
#include <cuda_runtime.h>
#include <cuda_fp16.h>
#include <math.h>
#include <stdint.h>

// ---------------- problem constants ----------------
#define NBLK 4
#define Bd   4
#define Sd   4096
#define Dd   1024
#define Ad   1024
#define FFd  4096
#define Md   (Bd*Sd)          // 16384 rows
#define RSPLIT 32             // splits per batch = row-groups of 128

// ---------------- scratch (device globals; allocation-free) ----------------
__device__ float g_bqkv[NBLK*3072];
__device__ __align__(256) __half g_qkvh[(size_t)Md*3072];   // only Q cols written
__device__ __align__(256) __half g_xh[(size_t)Md*Dd];
__device__ __align__(256) __half g_th[(size_t)Md*Dd];
__device__ __align__(256) __half g_vh[(size_t)Md*Ad];
__device__ __align__(256) __half g_hh[(size_t)Md*FFd];
// fp16 weights (transposed [N,K]): per block 12M halves
// fused qkv slot@0 (3M, K/V interleaved), o@3 (1M), w1@4 (4M), w2@8 (4M)
__device__ __align__(256) __half g_wf[(size_t)NBLK*12*1024*1024];
__device__ float g_pkv[RSPLIT*Bd*Ad], g_pks[RSPLIT*Bd*Ad];
__device__ float g_kv[Bd*Ad], g_ks[Bd*Ad];

#define WOFF(b, slot) ((size_t)(b)*12*1024*1024 + (size_t)(slot)*1024*1024)

// ---------------- PTX helpers (baseline PTX only) ----------------
__device__ __forceinline__ uint32_t smem_to_u32(const void* p) {
    uint32_t a;
    asm("{ .reg .u64 t; cvta.to.shared.u64 t, %1; cvt.u32.u64 %0, t; }" : "=r"(a) : "l"(p));
    return a;
}
__device__ __forceinline__ void cp16(uint32_t saddr, const void* gaddr) {
    asm volatile("cp.async.cg.shared.global [%0], [%1], 16;" :: "r"(saddr), "l"(gaddr) : "memory");
}
#define CP_COMMIT()  asm volatile("cp.async.commit_group;" ::: "memory")
#define CP_WAIT(n)   asm volatile("cp.async.wait_group %0;" :: "n"(n) : "memory")

__device__ __forceinline__ void ldsm4(uint32_t* r, uint32_t addr) {
    asm volatile("ldmatrix.sync.aligned.m8n8.x4.shared.b16 {%0,%1,%2,%3}, [%4];"
                 : "=r"(r[0]), "=r"(r[1]), "=r"(r[2]), "=r"(r[3]) : "r"(addr));
}
__device__ __forceinline__ void mma16816h(float* c, const uint32_t* a, const uint32_t* b) {
    asm volatile("mma.sync.aligned.m16n8k16.row.col.f32.f16.f16.f32 "
                 "{%0,%1,%2,%3}, {%4,%5,%6,%7}, {%8,%9}, {%0,%1,%2,%3};"
                 : "+f"(c[0]), "+f"(c[1]), "+f"(c[2]), "+f"(c[3])
                 : "r"(a[0]), "r"(a[1]), "r"(a[2]), "r"(a[3]), "r"(b[0]), "r"(b[1]));
}

// ---------------- math helpers ----------------
__device__ __forceinline__ float fast_rcp(float y) {
    float r = __uint_as_float(0x7EF311C3u - __float_as_uint(y));
    r = r * (2.0f - y * r);
    r = r * (2.0f - y * r);
    return r;
}
__device__ __forceinline__ float gelu_f(float x) {
    float u = 0.7978845608028654f * (x + 0.044715f * x * x * x);
    float uc = fminf(u, 9.0f);
    float e = exp2f(2.8853900817779268f * uc);   // e^(2u)
    float t = 1.0f - 2.0f * fast_rcp(e + 1.0f);
    return 0.5f * x * (1.0f + t);
}
__device__ __forceinline__ float elu1_f(float c) {
    return (c > 0.0f) ? (c + 1.0f) : __expf(c);
}
__device__ __forceinline__ float act_apply(float c, int ACT) {
    if (ACT == 1) return elu1_f(c);
    if (ACT == 2) return gelu_f(c);
    if (ACT == 3) return gelu_f(gelu_f(c));
    return c;
}

// ================= 1-product fp16 HMMA GEMM (fp16 out) =================
// ACT==4: fused QKV kernel. bx<8 => Q (elu+1, writes Ch). bx>=8 => K/V tile
// (K cols local 0-63 elu+1, V cols 64-127 identity); computes per-CTA partial
// KV/Ksum over its 128 rows in smem and writes g_pkv/g_pks; no global C write.
#define BKg    64
#define ROWB   144                  // 128B data + 16B pad -> conflict-free ldmatrix
#define TILEB  (128*ROWB)           // 18432 B
#define STAGEB (2*TILEB)            // A, W = 36864 B
#define GEMM_SMEM (2*STAGEB)        // 73728 B per CTA -> 2 CTAs/SM

template<int ACT>
__global__ void __launch_bounds__(256, 2)
gemm_mma(const __half* __restrict__ Ax, const __half* __restrict__ Bf,
         const float* __restrict__ bias, __half* __restrict__ Ch,
         int K, int N)
{
    extern __shared__ char smem[];
    const uint32_t sb = smem_to_u32(smem);
    const int tid = threadIdx.x, lane = tid & 31, warp = tid >> 5;
    const int wm = warp >> 2, wn = warp & 3;
    const int bx = blockIdx.x, by = blockIdx.y;

    float acc[4][4][4];
    #pragma unroll
    for (int i = 0; i < 4; i++)
        #pragma unroll
        for (int j = 0; j < 4; j++)
            #pragma unroll
            for (int k = 0; k < 4; k++) acc[i][j][k] = 0.0f;

    const __half* gp0 = Ax + (size_t)by*128*K;
    const __half* gp1 = Bf + (size_t)bx*128*K;

    auto load_stage = [&](int s, int kt) {
        #pragma unroll
        for (int i = 0; i < 8; i++) {
            int cid  = tid + i*256;
            int t    = cid >> 10;
            int slot = cid & 1023;
            int row  = slot >> 3;
            int c    = slot & 7;
            uint32_t sa = sb + s*STAGEB + t*TILEB + row*ROWB + c*16;
            const __half* g = (t == 0 ? gp0 : gp1);
            cp16(sa, g + (size_t)row*K + kt + c*8);
        }
        CP_COMMIT();
    };

    auto compute = [&](int s) {
        const uint32_t base = sb + s*STAGEB;
        const int l16 = lane & 15, lh = lane >> 4;
        const int brow = ((lane >> 4) & 1)*8 + (lane & 7);
        const int bc16 = (lane >> 3) & 1;
        #pragma unroll
        for (int ks = 0; ks < 4; ks++) {
            uint32_t ar[4][4], br[4][2];
            #pragma unroll
            for (int mi = 0; mi < 4; mi++) {
                uint32_t ad = base + (uint32_t)(wm*64 + mi*16 + l16)*ROWB + (ks*2 + lh)*16;
                ldsm4(ar[mi], ad);
            }
            #pragma unroll
            for (int np = 0; np < 2; np++) {
                uint32_t bd = base + TILEB
                            + (uint32_t)(wn*32 + np*16 + brow)*ROWB + (ks*2 + bc16)*16;
                ldsm4(&br[np*2][0], bd);
            }
            #pragma unroll
            for (int mi = 0; mi < 4; mi++)
                #pragma unroll
                for (int ni = 0; ni < 4; ni++)
                    mma16816h(acc[mi][ni], ar[mi], br[ni]);
        }
    };

    const int nk = K / BKg;
    load_stage(0, 0);
    for (int c = 0; c < nk; c++) {
        CP_WAIT(0);
        __syncthreads();
        if (c + 1 < nk) load_stage((c + 1) & 1, (c + 1) * BKg);
        compute(c & 1);
    }

    const int row0 = by*128 + wm*64, col0 = bx*128 + wn*32;
    const int cl = (lane & 3) * 2, rl = lane >> 2;

    if (ACT == 4 && bx >= 8) {
        // ---- K/V tile: stage to smem with act, then partial KV/Ksum ----
        __syncthreads();                       // mainloop smem reads done
        float* S = (float*)smem;               // 128 rows x 132 cols fp32
        #pragma unroll
        for (int ni = 0; ni < 4; ni++) {
            const int lc = wn*32 + ni*8 + cl;  // local col 0..127 (K<64, V>=64)
            const int gc = bx*128 + lc;
            const float b0 = bias[gc], b1 = bias[gc+1];
            const bool isK = (lc < 64);
            #pragma unroll
            for (int mi = 0; mi < 4; mi++) {
                const int lr = wm*64 + mi*16 + rl;
                float v0 = acc[mi][ni][0] + b0, v1 = acc[mi][ni][1] + b1;
                float v2 = acc[mi][ni][2] + b0, v3 = acc[mi][ni][3] + b1;
                if (isK) { v0 = elu1_f(v0); v1 = elu1_f(v1); v2 = elu1_f(v2); v3 = elu1_f(v3); }
                S[lr*132 + lc]     = v0;
                S[lr*132 + lc+1]   = v1;
                S[(lr+8)*132 + lc]   = v2;
                S[(lr+8)*132 + lc+1] = v3;
            }
        }
        __syncthreads();
        // 4 threads per h-col, each sums 32 rows (fixed order), tree combine
        const int h = tid & 63, q = tid >> 6;
        float kv = 0.0f, ks = 0.0f;
        #pragma unroll 4
        for (int r = q*32; r < q*32 + 32; r++) {
            float kk = S[r*132 + h];
            float vv = S[r*132 + 64 + h];
            kv = fmaf(kk, vv, kv);
            ks += kk;
        }
        float* R = S + 128*132;                // 512 floats of scratch
        R[q*64 + h] = kv;
        R[256 + q*64 + h] = ks;
        __syncthreads();
        if (tid < 64) {
            float kvt = ((R[tid] + R[64+tid]) + (R[128+tid] + R[192+tid]));
            float kst = ((R[256+tid] + R[320+tid]) + (R[384+tid] + R[448+tid]));
            const int b = by >> 5, split = by & 31;
            const int hg = (bx - 8)*64 + tid;
            g_pkv[(size_t)split*(Bd*Ad) + b*1024 + hg] = kvt;
            g_pks[(size_t)split*(Bd*Ad) + b*1024 + hg] = kst;
        }
        return;
    }

    const int actm = (ACT == 4) ? 1 : ACT;     // bx<8 of QKV => Q => elu+1
    #pragma unroll
    for (int ni = 0; ni < 4; ni++) {
        const int gc = col0 + ni*8 + cl;
        const float b0 = bias[gc], b1 = bias[gc+1];
        #pragma unroll
        for (int mi = 0; mi < 4; mi++) {
            const int gr = row0 + mi*16 + rl;
            float v0 = act_apply(acc[mi][ni][0] + b0, actm);
            float v1 = act_apply(acc[mi][ni][1] + b1, actm);
            float v2 = act_apply(acc[mi][ni][2] + b0, actm);
            float v3 = act_apply(acc[mi][ni][3] + b1, actm);
            __half2 hp0 = __halves2half2(__float2half_rn(v0), __float2half_rn(v1));
            __half2 hp1 = __halves2half2(__float2half_rn(v2), __float2half_rn(v3));
            *(uint32_t*)(Ch + (size_t)gr*N + gc)     = *(uint32_t*)&hp0;
            *(uint32_t*)(Ch + (size_t)(gr+8)*N + gc) = *(uint32_t*)&hp1;
        }
    }
}

// ================= prep kernels ======
// fused QKV col layout: p<1024: Q col p. p>=1024: g=(p-1024)/128, j=(p-1024)%128;
// j<64 -> K col g*64+j ; j>=64 -> V col g*64+(j-64).
#define PREP_WTILES 12288
__global__ void __launch_bounds__(256)
prep_w(const float* __restrict__ Wq, const float* __restrict__ Wk,
       const float* __restrict__ Wv, const float* __restrict__ Wo,
       const float* __restrict__ W1, const float* __restrict__ W2)
{
    const int t = blockIdx.x, tid = threadIdx.x;
    __shared__ float s[32][133];
    const int i = t / 3072, r = t % 3072;
    const float* src; int K, N, kb, nb; size_t doff; int m = -1;
    if (r < 1024) {
        m = r >> 8; const int tile = r & 255;
        src = (m==0 ? Wq : m==1 ? Wk : m==2 ? Wv : Wo) + (size_t)i*1024*1024;
        K = 1024; N = 1024;
        doff = (m == 3) ? WOFF(i, 3) : WOFF(i, 0);
        kb = tile >> 3; nb = tile & 7;
    } else if (r < 2048) {
        const int tile = r - 1024;
        src = W1 + (size_t)i*4*1024*1024;
        K = 1024; N = 4096; doff = WOFF(i, 4);
        kb = tile >> 5; nb = tile & 31;
    } else {
        const int tile = r - 2048;
        src = W2 + (size_t)i*4*1024*1024;
        K = 4096; N = 1024; doff = WOFF(i, 8);
        kb = tile >> 3; nb = tile & 7;
    }
    const int k0 = kb*32, n0 = nb*128;
    #pragma unroll
    for (int j = 0; j < 4; j++) {
        int q  = tid + j*256;
        int rr = q >> 5;
        int cc = (q & 31) * 4;
        float4 v = *(const float4*)(src + (size_t)(k0+rr)*N + n0 + cc);
        s[rr][cc]   = v.x;
        s[rr][cc+1] = v.y;
        s[rr][cc+2] = v.z;
        s[rr][cc+3] = v.w;
    }
    __syncthreads();
    const int n = tid >> 1, kk = (tid & 1) * 16;
    __half hb[16];
    #pragma unroll
    for (int e = 0; e < 16; e++) hb[e] = __float2half_rn(s[kk + e][n]);
    int ng = n0 + n;                    // source output-col index
    size_t prow;
    if (m == 1)      prow = 1024 + (size_t)(ng >> 6)*128 + (ng & 63);        // K
    else if (m == 2) prow = 1024 + (size_t)(ng >> 6)*128 + 64 + (ng & 63);   // V
    else             prow = ng;         // Q / Wo / W1 / W2
    __half* Th = g_wf + doff + prow*K + k0 + kk;
    *(uint4*)(Th)     = *(uint4*)(hb);
    *(uint4*)(Th + 8) = *(uint4*)(hb + 8);
}

__global__ void __launch_bounds__(256)
prep_x(const float* __restrict__ x)
{
    const size_t c = blockIdx.x;
    const float4* x4 = (const float4*)x;
    #pragma unroll
    for (int j = 0; j < 2; j++) {
        size_t id = c*512 + threadIdx.x + j*256;
        float4 v = x4[id];
        __half h[4];
        h[0] = __float2half_rn(v.x);
        h[1] = __float2half_rn(v.y);
        h[2] = __float2half_rn(v.z);
        h[3] = __float2half_rn(v.w);
        *(uint2*)(g_xh + id*4) = *(uint2*)h;
    }
}

__global__ void __launch_bounds__(256)
prep_b(const float* __restrict__ bq, const float* __restrict__ bk,
       const float* __restrict__ bv)
{
    #pragma unroll
    for (int j = 0; j < 8; j++) {
        int id = blockIdx.x*2048 + threadIdx.x + j*256;
        int i  = id / 3072, n = id % 3072;
        float v;
        if (n < 1024) v = bq[i*1024 + n];
        else {
            int g = (n - 1024) >> 7, jj = (n - 1024) & 127;
            v = (jj < 64) ? bk[i*1024 + g*64 + jj]
                          : bv[i*1024 + g*64 + (jj - 64)];
        }
        g_bqkv[id] = v;
    }
}

// ---------------- final KV/Ksum: sum 32 splits -------------------------------
__global__ void __launch_bounds__(256) reduce_stage2()
{
    const int tid = threadIdx.x;
    const int h = blockIdx.x * 64 + (tid >> 2);
    const int p = tid & 3;
    float kv = 0.0f, ks = 0.0f;
    #pragma unroll
    for (int s = p; s < RSPLIT; s += 4) {
        kv += g_pkv[(size_t)s * (Bd*Ad) + h];
        ks += g_pks[(size_t)s * (Bd*Ad) + h];
    }
    kv += __shfl_xor_sync(0xffffffffu, kv, 1);
    kv += __shfl_xor_sync(0xffffffffu, kv, 2);
    ks += __shfl_xor_sync(0xffffffffu, ks, 1);
    ks += __shfl_xor_sync(0xffffffffu, ks, 2);
    if (p == 0) { g_kv[h] = kv; g_ks[h] = ks; }
}

// ---------------- V' = Q*KV/(Q*Ksum+1e-6) -> fp16 (vectorized x4) -----------
__global__ void __launch_bounds__(256)
attn_v(const __half* __restrict__ qkv, __half* __restrict__ vh)
{
    const int idx4 = blockIdx.x * 256 + threadIdx.x;
    const int row = idx4 >> 8, hq = (idx4 & 255) * 4;
    const int b   = row >> 12;
    uint2 qraw = *(const uint2*)(qkv + (size_t)row*3072 + hq);
    __half2 q01 = *(__half2*)&qraw.x, q23 = *(__half2*)&qraw.y;
    float4 kvv = *(const float4*)(g_kv + b*Ad + hq);
    float4 ksv = *(const float4*)(g_ks + b*Ad + hq);
    float Q0 = __low2float(q01), Q1 = __high2float(q01);
    float Q2 = __low2float(q23), Q3 = __high2float(q23);
    float V0 = Q0 * kvv.x / (Q0 * ksv.x + 1e-6f);
    float V1 = Q1 * kvv.y / (Q1 * ksv.y + 1e-6f);
    float V2 = Q2 * kvv.z / (Q2 * ksv.z + 1e-6f);
    float V3 = Q3 * kvv.w / (Q3 * ksv.w + 1e-6f);
    __half2 o01 = __halves2half2(__float2half_rn(V0), __float2half_rn(V1));
    __half2 o23 = __halves2half2(__float2half_rn(V2), __float2half_rn(V3));
    uint2 ov = make_uint2(*(uint32_t*)&o01, *(uint32_t*)&o23);
    *(uint2*)(vh + (size_t)row*Ad + hq) = ov;
}

// ---------------- LN(a + r)*s + b; fp16 in, fp16 out (+opt fp32 final) ------
__global__ void __launch_bounds__(256)
add_layernorm(const __half* __restrict__ a, const __half* __restrict__ r,
              const float* __restrict__ s, const float* __restrict__ b,
              __half* __restrict__ oh, float* __restrict__ outf)
{
    __shared__ float sm[8];
    const int tid = threadIdx.x;
    const size_t base = (size_t)blockIdx.x * Dd;

    float v[4];
    float lsum = 0.0f;
    #pragma unroll
    for (int j = 0; j < 2; j++) {
        int i = tid*2 + j*512;
        __half2 av = *(const __half2*)(a + base + i);
        __half2 rv = *(const __half2*)(r + base + i);
        v[j*2]   = __low2float(av)  + __low2float(rv);
        v[j*2+1] = __high2float(av) + __high2float(rv);
        lsum += v[j*2] + v[j*2+1];
    }
    #pragma unroll
    for (int o = 16; o > 0; o >>= 1) lsum += __shfl_xor_sync(0xffffffffu, lsum, o);
    if ((tid & 31) == 0) sm[tid >> 5] = lsum;
    __syncthreads();
    float tot = 0.0f;
    #pragma unroll
    for (int w = 0; w < 8; w++) tot += sm[w];
    const float mean = tot * (1.0f / Dd);
    __syncthreads();

    float lvar = 0.0f;
    #pragma unroll
    for (int j = 0; j < 4; j++) { float d = v[j] - mean; lvar += d*d; }
    #pragma unroll
    for (int o = 16; o > 0; o >>= 1) lvar += __shfl_xor_sync(0xffffffffu, lvar, o);
    if ((tid & 31) == 0) sm[tid >> 5] = lvar;
    __syncthreads();
    float vtot = 0.0f;
    #pragma unroll
    for (int w = 0; w < 8; w++) vtot += sm[w];
    const float rstd = rsqrtf(vtot * (1.0f / Dd) + 1e-6f);

    #pragma unroll
    for (int j = 0; j < 2; j++) {
        int i = tid*2 + j*512;
        float o0 = (v[j*2]   - mean) * rstd * s[i]   + b[i];
        float o1 = (v[j*2+1] - mean) * rstd * s[i+1] + b[i+1];
        __half2 ov = __halves2half2(__float2half_rn(o0), __float2half_rn(o1));
        *(__half2*)(oh + base + i) = ov;
        if (outf) *(float2*)(outf + base + i) = make_float2(o0, o1);
    }
}

// ---------------- launcher ----------------
extern "C" void kernel_launch(void* const* d_in, const int* in_sizes, int n_in,
                              void* d_out, int out_size)
{
    const float* x     = (const float*)d_in[0];
    const float* Wq    = (const float*)d_in[1];
    const float* bq    = (const float*)d_in[2];
    const float* Wk    = (const float*)d_in[3];
    const float* bk    = (const float*)d_in[4];
    const float* Wv    = (const float*)d_in[5];
    const float* bv    = (const float*)d_in[6];
    const float* Wo    = (const float*)d_in[7];
    const float* bo    = (const float*)d_in[8];
    const float* ln1_s = (const float*)d_in[9];
    const float* ln1_b = (const float*)d_in[10];
    const float* W1    = (const float*)d_in[11];
    const float* b1    = (const float*)d_in[12];
    const float* W2    = (const float*)d_in[13];
    const float* b2    = (const float*)d_in[14];
    const float* ln2_s = (const float*)d_in[15];
    const float* ln2_b = (const float*)d_in[16];
    float* out = (float*)d_out;

    float *gbq;
    __half *gqkvh, *gxh, *gth, *gvh, *ghh, *gwf;
    cudaGetSymbolAddress((void**)&gbq,   g_bqkv);
    cudaGetSymbolAddress((void**)&gqkvh, g_qkvh);
    cudaGetSymbolAddress((void**)&gxh,   g_xh);
    cudaGetSymbolAddress((void**)&gth,   g_th);
    cudaGetSymbolAddress((void**)&gvh,   g_vh);
    cudaGetSymbolAddress((void**)&ghh,   g_hh);
    cudaGetSymbolAddress((void**)&gwf,   g_wf);

    cudaFuncSetAttribute(gemm_mma<4>, cudaFuncAttributeMaxDynamicSharedMemorySize, GEMM_SMEM);
    cudaFuncSetAttribute(gemm_mma<3>, cudaFuncAttributeMaxDynamicSharedMemorySize, GEMM_SMEM);
    cudaFuncSetAttribute(gemm_mma<2>, cudaFuncAttributeMaxDynamicSharedMemorySize, GEMM_SMEM);

    // prep as 3 launches (0,1,2) so the QKV GEMM lands at the profiled slot
    prep_w<<<PREP_WTILES, 256>>>(Wq, Wk, Wv, Wo, W1, W2);
    prep_x<<<8192, 256>>>(x);
    prep_b<<<6, 256>>>(bq, bk, bv);

    const dim3 gQKV(3072/128, Md/128);       // 24 x 128
    const dim3 gA(Ad/128,  Md/128);          // 8 x 128
    const dim3 gF(FFd/128, Md/128);          // 32 x 128

    for (int i = 0; i < NBLK; i++) {
        // fused QKV + in-epilogue KV/Ksum partials
        gemm_mma<4><<<gQKV, 256, GEMM_SMEM>>>(gxh, gwf + WOFF(i,0),
                                              gbq + i*3072, gqkvh, Dd, 3072);

        reduce_stage2<<<(Bd*Ad)/64, 256>>>();
        attn_v<<<((size_t)Md*Ad/4)/256, 256>>>(gqkvh, gvh);

        // a = gelu(gelu(V@Wo + bo))  -> fp16
        gemm_mma<3><<<gA, 256, GEMM_SMEM>>>(gvh, gwf + WOFF(i,3),
                                            bo + (size_t)i*Dd, gth, Ad, Dd);
        add_layernorm<<<Md, 256>>>(gth, gxh, ln1_s + (size_t)i*Dd, ln1_b + (size_t)i*Dd,
                                   gxh, nullptr);

        // h = gelu(x@W1+b1) ; f = gelu(h@W2+b2)  -> fp16
        gemm_mma<2><<<gF, 256, GEMM_SMEM>>>(gxh, gwf + WOFF(i,4),
                                            b1 + (size_t)i*FFd, ghh, Dd, FFd);
        gemm_mma<2><<<gA, 256, GEMM_SMEM>>>(ghh, gwf + WOFF(i,8),
                                            b2 + (size_t)i*Dd, gth, FFd, Dd);

        // x = LN(f + x); final block also writes fp32 output
        float* outf = (i == NBLK-1) ? out : nullptr;
        add_layernorm<<<Md, 256>>>(gth, gxh, ln2_s + (size_t)i*Dd, ln2_b + (size_t)i*Dd,
                                   gxh, outf);
    }
}